// round 8
// baseline (speedup 1.0000x reference)
#include <cuda_runtime.h>

#define EPS    1e-5f
#define V_DIM  32
#define D_DIM  128
#define NPER   32          // n-units (16KB each) per CTA, processed 4 at a time

// ---------------------------------------------------------------------------
// 1024-thread CTA = 32 warps; warp w owns variable v = w. Each CTA iteration
// writes a CONTIGUOUS 64KB block (4 n-units) — dense CTA write footprint
// (R4/R6 vs R5 evidence). Lanes hold W/b/gamma/beta[v, lane*4..+3] in regs;
// warp computes per-v stats once via shuffles (analytic LayerNorm):
//   h  = x*W + b ;  mu = x*Wbar + bbar ;  var = x^2 VarW + 2x Cov + Varb
// R8 change vs R7: __stwt (write-through) instead of __stcs — the output is
// write-once; skip L2 dirty-line allocation/writeback entirely.
// ---------------------------------------------------------------------------
__global__ void __launch_bounds__(1024, 1)
ve_kernel(const float* __restrict__ x,
          const float* __restrict__ W,
          const float* __restrict__ b,
          const float* __restrict__ gamma,
          const float* __restrict__ beta,
          float* __restrict__ out) {
    int v    = threadIdx.x >> 5;     // warp id = variable index
    int lane = threadIdx.x & 31;

    int t = v * 32 + lane;           // [V, D/4] table index
    float4 w4 = __ldg(reinterpret_cast<const float4*>(W)     + t);
    float4 b4 = __ldg(reinterpret_cast<const float4*>(b)     + t);
    float4 g4 = __ldg(reinterpret_cast<const float4*>(gamma) + t);
    float4 e4 = __ldg(reinterpret_cast<const float4*>(beta)  + t);

    // ---- per-v stats via butterfly reductions ----
    float sw = w4.x + w4.y + w4.z + w4.w;
    float sb = b4.x + b4.y + b4.z + b4.w;
    #pragma unroll
    for (int off = 16; off > 0; off >>= 1) {
        sw += __shfl_xor_sync(0xFFFFFFFFu, sw, off);
        sb += __shfl_xor_sync(0xFFFFFFFFu, sb, off);
    }
    float Wbar = sw * (1.0f / D_DIM);
    float bbar = sb * (1.0f / D_DIM);

    float wc0 = w4.x - Wbar, wc1 = w4.y - Wbar, wc2 = w4.z - Wbar, wc3 = w4.w - Wbar;
    float bc0 = b4.x - bbar, bc1 = b4.y - bbar, bc2 = b4.z - bbar, bc3 = b4.w - bbar;
    float sww = wc0*wc0 + wc1*wc1 + wc2*wc2 + wc3*wc3;
    float swb = wc0*bc0 + wc1*bc1 + wc2*bc2 + wc3*bc3;
    float sbb = bc0*bc0 + bc1*bc1 + bc2*bc2 + bc3*bc3;
    #pragma unroll
    for (int off = 16; off > 0; off >>= 1) {
        sww += __shfl_xor_sync(0xFFFFFFFFu, sww, off);
        swb += __shfl_xor_sync(0xFFFFFFFFu, swb, off);
        sbb += __shfl_xor_sync(0xFFFFFFFFu, sbb, off);
    }
    float varW = sww * (1.0f / D_DIM);
    float cov2 = swb * (2.0f / D_DIM);   // 2*Cov(W,b)
    float varb = sbb * (1.0f / D_DIM);

    int n0 = blockIdx.x * NPER;
    const float* xp = x + (size_t)n0 * V_DIM + v;               // x[n*V + v]
    float4* orow = reinterpret_cast<float4*>(out)
                 + ((size_t)n0 * V_DIM + v) * 32 + lane;        // row base
    const int UNIT4 = V_DIM * 32;                                // float4s per n-unit

    #pragma unroll 2
    for (int i = 0; i < NPER / 4; i++) {
        // front-batch 4 independent x loads
        float xv0 = __ldg(xp + (size_t)(4 * i)     * V_DIM);
        float xv1 = __ldg(xp + (size_t)(4 * i + 1) * V_DIM);
        float xv2 = __ldg(xp + (size_t)(4 * i + 2) * V_DIM);
        float xv3 = __ldg(xp + (size_t)(4 * i + 3) * V_DIM);

        float rs0 = rsqrtf(fmaf(xv0, fmaf(xv0, varW, cov2), varb) + EPS);
        float rs1 = rsqrtf(fmaf(xv1, fmaf(xv1, varW, cov2), varb) + EPS);
        float rs2 = rsqrtf(fmaf(xv2, fmaf(xv2, varW, cov2), varb) + EPS);
        float rs3 = rsqrtf(fmaf(xv3, fmaf(xv3, varW, cov2), varb) + EPS);
        float nm0 = -fmaf(xv0, Wbar, bbar) * rs0;
        float nm1 = -fmaf(xv1, Wbar, bbar) * rs1;
        float nm2 = -fmaf(xv2, Wbar, bbar) * rs2;
        float nm3 = -fmaf(xv3, Wbar, bbar) * rs3;

        #define ROW_OUT(o, xv, rs, nm)                                        \
        {                                                                     \
            { float h = fmaf(w4.x, xv, b4.x); float y = fmaf(h, rs, nm);      \
              o.x = fmaxf(fmaf(g4.x, y, e4.x), 0.0f); }                       \
            { float h = fmaf(w4.y, xv, b4.y); float y = fmaf(h, rs, nm);      \
              o.y = fmaxf(fmaf(g4.y, y, e4.y), 0.0f); }                       \
            { float h = fmaf(w4.z, xv, b4.z); float y = fmaf(h, rs, nm);      \
              o.z = fmaxf(fmaf(g4.z, y, e4.z), 0.0f); }                       \
            { float h = fmaf(w4.w, xv, b4.w); float y = fmaf(h, rs, nm);      \
              o.w = fmaxf(fmaf(g4.w, y, e4.w), 0.0f); }                       \
        }

        float4 o0; ROW_OUT(o0, xv0, rs0, nm0);
        float4 o1; ROW_OUT(o1, xv1, rs1, nm1);
        __stwt(orow + (size_t)(4 * i)     * UNIT4, o0);
        __stwt(orow + (size_t)(4 * i + 1) * UNIT4, o1);
        float4 o2; ROW_OUT(o2, xv2, rs2, nm2);
        float4 o3; ROW_OUT(o3, xv3, rs3, nm3);
        __stwt(orow + (size_t)(4 * i + 2) * UNIT4, o2);
        __stwt(orow + (size_t)(4 * i + 3) * UNIT4, o3);

        #undef ROW_OUT
    }
}

// ---------------------------------------------------------------------------
extern "C" void kernel_launch(void* const* d_in, const int* in_sizes, int n_in,
                              void* d_out, int out_size) {
    const float* x     = (const float*)d_in[0];
    const float* W     = (const float*)d_in[1];
    const float* b     = (const float*)d_in[2];
    const float* gamma = (const float*)d_in[3];
    const float* beta  = (const float*)d_in[4];
    float* out = (float*)d_out;

    // n-units of 16KB = out_size / (V*D) = 32768 ; blocks = 32768/NPER = 1024
    int n_units = out_size / (V_DIM * D_DIM);
    int blocks  = n_units / NPER;

    ve_kernel<<<blocks, 1024>>>(x, W, b, gamma, beta, out);
}

// round 10
// speedup vs baseline: 1.0885x; 1.0885x over previous
#include <cuda_runtime.h>
#include <cstdint>

#define EPS    1e-5f
#define V_DIM  32
#define D_DIM  128
#define NPER   32          // n-units (16KB each) per CTA
#define NBUF   4           // pipeline depth

// ---------------------------------------------------------------------------
// 1024-thread CTA = 32 warps; warp w owns variable v = w. Register-resident
// tables + shuffle stats (analytic LayerNorm — no per-row reduction):
//   h = x*W + b ; mu = x*Wbar + bbar ; var = x^2 VarW + 2x Cov + Varb
// Each n-unit (all 32 v for one (b,s) = 16KB contiguous) is staged in smem
// and written with cp.async.bulk S2G carrying an L2 evict-first cache-policy
// hint (the R4-proven policy win) — bulk-engine linear 16KB writes replace
// per-warp STG bursts. 4-deep buffer pipeline keeps the copy engine fed.
// ---------------------------------------------------------------------------
__global__ void __launch_bounds__(1024, 1)
ve_kernel(const float* __restrict__ x,
          const float* __restrict__ W,
          const float* __restrict__ b,
          const float* __restrict__ gamma,
          const float* __restrict__ beta,
          float* __restrict__ out) {
    __shared__ __align__(1024) float sbuf[NBUF][V_DIM * D_DIM];  // 4 x 16KB

    int v    = threadIdx.x >> 5;     // warp id = variable index
    int lane = threadIdx.x & 31;

    int t = v * 32 + lane;           // [V, D/4] table index
    float4 w4 = __ldg(reinterpret_cast<const float4*>(W)     + t);
    float4 b4 = __ldg(reinterpret_cast<const float4*>(b)     + t);
    float4 g4 = __ldg(reinterpret_cast<const float4*>(gamma) + t);
    float4 e4 = __ldg(reinterpret_cast<const float4*>(beta)  + t);

    // ---- per-v stats via butterfly reductions ----
    float sw = w4.x + w4.y + w4.z + w4.w;
    float sb = b4.x + b4.y + b4.z + b4.w;
    #pragma unroll
    for (int off = 16; off > 0; off >>= 1) {
        sw += __shfl_xor_sync(0xFFFFFFFFu, sw, off);
        sb += __shfl_xor_sync(0xFFFFFFFFu, sb, off);
    }
    float Wbar = sw * (1.0f / D_DIM);
    float bbar = sb * (1.0f / D_DIM);

    float wc0 = w4.x - Wbar, wc1 = w4.y - Wbar, wc2 = w4.z - Wbar, wc3 = w4.w - Wbar;
    float bc0 = b4.x - bbar, bc1 = b4.y - bbar, bc2 = b4.z - bbar, bc3 = b4.w - bbar;
    float sww = wc0*wc0 + wc1*wc1 + wc2*wc2 + wc3*wc3;
    float swb = wc0*bc0 + wc1*bc1 + wc2*bc2 + wc3*bc3;
    float sbb = bc0*bc0 + bc1*bc1 + bc2*bc2 + bc3*bc3;
    #pragma unroll
    for (int off = 16; off > 0; off >>= 1) {
        sww += __shfl_xor_sync(0xFFFFFFFFu, sww, off);
        swb += __shfl_xor_sync(0xFFFFFFFFu, swb, off);
        sbb += __shfl_xor_sync(0xFFFFFFFFu, sbb, off);
    }
    float varW = sww * (1.0f / D_DIM);
    float cov2 = swb * (2.0f / D_DIM);   // 2*Cov(W,b)
    float varb = sbb * (1.0f / D_DIM);

    // L2 evict-first cache policy for the bulk stores
    uint64_t pol;
    asm("createpolicy.fractional.L2::evict_first.b64 %0, 1.0;" : "=l"(pol));

    const float* xp = x + v;             // x[n*V + v]
    int n0 = blockIdx.x * NPER;

    uint32_t sa[NBUF];
    #pragma unroll
    for (int k = 0; k < NBUF; k++) {
        asm("{ .reg .u64 tt; cvta.to.shared.u64 tt, %1; cvt.u32.u64 %0, tt; }"
            : "=r"(sa[k]) : "l"(&sbuf[k][0]));
    }

    for (int i = 0; i < NPER; i++) {
        int n  = n0 + i;
        int bf = i & (NBUF - 1);

        // ---- compute this warp's 512B row (overlaps in-flight copies) ----
        float xv  = __ldg(xp + (size_t)n * V_DIM);
        float var = fmaf(xv, fmaf(xv, varW, cov2), varb);
        float rs  = rsqrtf(var + EPS);
        float nmr = -fmaf(xv, Wbar, bbar) * rs;

        float4 o;
        { float h = fmaf(w4.x, xv, b4.x); float y = fmaf(h, rs, nmr);
          o.x = fmaxf(fmaf(g4.x, y, e4.x), 0.0f); }
        { float h = fmaf(w4.y, xv, b4.y); float y = fmaf(h, rs, nmr);
          o.y = fmaxf(fmaf(g4.y, y, e4.y), 0.0f); }
        { float h = fmaf(w4.z, xv, b4.z); float y = fmaf(h, rs, nmr);
          o.z = fmaxf(fmaf(g4.z, y, e4.z), 0.0f); }
        { float h = fmaf(w4.w, xv, b4.w); float y = fmaf(h, rs, nmr);
          o.w = fmaxf(fmaf(g4.w, y, e4.w), 0.0f); }

        // ---- backpressure: buffer bf free once <= NBUF-1 copies pending ----
        if (threadIdx.x == 0) {
            asm volatile("cp.async.bulk.wait_group.read %0;" :: "n"(NBUF - 1) : "memory");
        }
        __syncthreads();

        // ---- stage into smem (layout == gmem layout for this n-unit) ----
        reinterpret_cast<float4*>(&sbuf[bf][v * D_DIM])[lane] = o;
        __syncthreads();

        // ---- bulk copy 16KB smem -> gmem with evict-first hint ----
        if (threadIdx.x == 0) {
            asm volatile("fence.proxy.async.shared::cta;" ::: "memory");
            const float* gdst = out + (size_t)n * (V_DIM * D_DIM);
            int bytes = V_DIM * D_DIM * 4;
            asm volatile(
                "cp.async.bulk.global.shared::cta.bulk_group.L2::cache_hint "
                "[%0], [%1], %2, %3;"
                :: "l"(gdst), "r"(sa[bf]), "r"(bytes), "l"(pol) : "memory");
            asm volatile("cp.async.bulk.commit_group;" ::: "memory");
        }
    }

    if (threadIdx.x == 0) {
        asm volatile("cp.async.bulk.wait_group.read 0;" ::: "memory");
    }
}

// ---------------------------------------------------------------------------
extern "C" void kernel_launch(void* const* d_in, const int* in_sizes, int n_in,
                              void* d_out, int out_size) {
    const float* x     = (const float*)d_in[0];
    const float* W     = (const float*)d_in[1];
    const float* b     = (const float*)d_in[2];
    const float* gamma = (const float*)d_in[3];
    const float* beta  = (const float*)d_in[4];
    float* out = (float*)d_out;

    // n-units of 16KB = out_size / (V*D) = 32768 ; blocks = 32768/NPER = 1024
    int n_units = out_size / (V_DIM * D_DIM);
    int blocks  = n_units / NPER;

    ve_kernel<<<blocks, 1024>>>(x, W, b, gamma, beta, out);
}